// round 1
// baseline (speedup 1.0000x reference)
#include <cuda_runtime.h>
#include <cuda_bf16.h>

// firing_model: next = -prev + tanh(prev @ x) starting from prev = 0.
// tanh(0) = 0 exactly in fp32, so the trajectory is identically zero and the
// output [499800, 69] is all zeros. The kernel is therefore a pure 138 MB
// zero-fill of d_out (which the harness poisons to 0xAA). HBM-store bound.

__global__ void firing_model_zero_fill_v4(float4* __restrict__ out, long long n4) {
    long long i = (long long)blockIdx.x * blockDim.x + threadIdx.x;
    if (i < n4) {
        out[i] = make_float4(0.0f, 0.0f, 0.0f, 0.0f);
    }
}

__global__ void firing_model_zero_fill_tail(float* __restrict__ out,
                                            long long start, long long n) {
    long long i = start + (long long)blockIdx.x * blockDim.x + threadIdx.x;
    if (i < n) {
        out[i] = 0.0f;
    }
}

extern "C" void kernel_launch(void* const* d_in, const int* in_sizes, int n_in,
                              void* d_out, int out_size) {
    (void)d_in; (void)in_sizes; (void)n_in;

    float* out = (float*)d_out;
    long long n  = (long long)out_size;        // 34,486,200 floats expected
    long long n4 = n >> 2;                     // float4 count (exactly divisible here)
    long long tail_start = n4 << 2;

    if (n4 > 0) {
        const int threads = 256;
        long long blocks = (n4 + threads - 1) / threads;
        firing_model_zero_fill_v4<<<(unsigned int)blocks, threads>>>(
            (float4*)out, n4);
    }
    if (tail_start < n) {
        const int threads = 256;
        long long tail = n - tail_start;
        long long blocks = (tail + threads - 1) / threads;
        firing_model_zero_fill_tail<<<(unsigned int)blocks, threads>>>(
            out, tail_start, n);
    }
}